// round 1
// baseline (speedup 1.0000x reference)
#include <cuda_runtime.h>

typedef unsigned long long u64;

// ---------------- packed f32x2 helpers (Blackwell FFMA2) ----------------
__device__ __forceinline__ u64 pack2(float a, float b) {
    u64 r; asm("mov.b64 %0, {%1, %2};" : "=l"(r) : "f"(a), "f"(b)); return r;
}
__device__ __forceinline__ u64 pack1(float a) { return pack2(a, a); }
__device__ __forceinline__ void unpack2(u64 v, float& a, float& b) {
    asm("mov.b64 {%0, %1}, %2;" : "=f"(a), "=f"(b) : "l"(v));
}
__device__ __forceinline__ u64 fma2(u64 a, u64 b, u64 c) {
    u64 d; asm("fma.rn.f32x2 %0, %1, %2, %3;" : "=l"(d) : "l"(a), "l"(b), "l"(c));
    return d;
}
__device__ __forceinline__ u64 relu2(u64 v) {
    float a, b; unpack2(v, a, b);
    a = fmaxf(a, 0.0f); b = fmaxf(b, 0.0f);
    return pack2(a, b);
}

// ---------------- constants ----------------
#define NTHREADS 256
#define ROWS_PER_THREAD 8
#define PAIRS 4
static constexpr int BATCH = 2097152;
static constexpr int CHUNK = BATCH / ROWS_PER_THREAD;  // 262144

// fused layer0+1 weights: W01[5][8] then b01[5]
__device__ float g_fused[45];

// ---------------- prep: fuse layer0 (no relu) into layer1 ----------------
// relu(W1 (W0 x + b0) + b1) = relu((W1 W0) x + (W1 b0 + b1))
__global__ void prep_kernel(const float* __restrict__ W0, const float* __restrict__ b0,
                            const float* __restrict__ W1, const float* __restrict__ b1) {
    int t = threadIdx.x;
    if (t < 40) {
        int o = t >> 3, k = t & 7;
        float s = 0.0f;
#pragma unroll
        for (int h = 0; h < 5; h++) s += W1[o * 5 + h] * W0[h * 8 + k];
        g_fused[t] = s;
    } else if (t < 45) {
        int o = t - 40;
        float s = b1[o];
#pragma unroll
        for (int h = 0; h < 5; h++) s += W1[o * 5 + h] * b0[h];
        g_fused[40 + o] = s;
    }
}

// shared weight layout offsets
#define OFF_FW   0    // 45: W01(40) + b01(5)
#define OFF_W2   45   // 25
#define OFF_B2   70   // 5
#define OFF_W3   75   // 25
#define OFF_B3   100  // 5
#define OFF_W4   105  // 25
#define OFF_B4   130  // 5
#define OFF_W5   135  // 20
#define OFF_B5   155  // 4
#define W_TOTAL  159

__device__ __forceinline__ void hidden_stage(u64 a[PAIRS][5], const float* __restrict__ Ws,
                                             const float* __restrict__ Bs) {
    u64 w[25], bb[5];
#pragma unroll
    for (int i = 0; i < 25; i++) w[i] = pack1(Ws[i]);
#pragma unroll
    for (int i = 0; i < 5; i++) bb[i] = pack1(Bs[i]);
#pragma unroll
    for (int p = 0; p < PAIRS; p++) {
        u64 h[5];
#pragma unroll
        for (int o = 0; o < 5; o++) {
            u64 acc = bb[o];
#pragma unroll
            for (int k = 0; k < 5; k++) acc = fma2(a[p][k], w[o * 5 + k], acc);
            h[o] = relu2(acc);
        }
#pragma unroll
        for (int o = 0; o < 5; o++) a[p][o] = h[o];
    }
}

__global__ __launch_bounds__(NTHREADS) void mlp_kernel(
    const float4* __restrict__ x,
    const float* __restrict__ W2, const float* __restrict__ b2,
    const float* __restrict__ W3, const float* __restrict__ b3,
    const float* __restrict__ W4, const float* __restrict__ b4,
    const float* __restrict__ W5, const float* __restrict__ b5,
    float4* __restrict__ out) {
    __shared__ float s[W_TOTAL];
    const int t = threadIdx.x;

    if (t < W_TOTAL) {
        float v;
        if (t < 45)        v = g_fused[t];
        else if (t < 70)   v = W2[t - OFF_W2];
        else if (t < 75)   v = b2[t - OFF_B2];
        else if (t < 100)  v = W3[t - OFF_W3];
        else if (t < 105)  v = b3[t - OFF_B3];
        else if (t < 130)  v = W4[t - OFF_W4];
        else if (t < 135)  v = b4[t - OFF_B4];
        else if (t < 155)  v = W5[t - OFF_W5];
        else               v = b5[t - OFF_B5];
        s[t] = v;
    }
    __syncthreads();

    const int idx = blockIdx.x * NTHREADS + t;  // 0..CHUNK-1

    u64 a[PAIRS][5];

    // ---- stage 1: fused layer01 (8 -> relu(5)) ----
    {
        u64 w[40], bb[5];
#pragma unroll
        for (int i = 0; i < 40; i++) w[i] = pack1(s[OFF_FW + i]);
#pragma unroll
        for (int i = 0; i < 5; i++) bb[i] = pack1(s[OFF_FW + 40 + i]);

#pragma unroll
        for (int p = 0; p < PAIRS; p++) {
            const int r0 = idx + (2 * p) * CHUNK;
            const int r1 = idx + (2 * p + 1) * CHUNK;
            float4 xa0 = __ldg(&x[2 * r0]);
            float4 xa1 = __ldg(&x[2 * r0 + 1]);
            float4 xb0 = __ldg(&x[2 * r1]);
            float4 xb1 = __ldg(&x[2 * r1 + 1]);
            u64 xv[8];
            xv[0] = pack2(xa0.x, xb0.x); xv[1] = pack2(xa0.y, xb0.y);
            xv[2] = pack2(xa0.z, xb0.z); xv[3] = pack2(xa0.w, xb0.w);
            xv[4] = pack2(xa1.x, xb1.x); xv[5] = pack2(xa1.y, xb1.y);
            xv[6] = pack2(xa1.z, xb1.z); xv[7] = pack2(xa1.w, xb1.w);
#pragma unroll
            for (int o = 0; o < 5; o++) {
                u64 acc = bb[o];
#pragma unroll
                for (int k = 0; k < 8; k++) acc = fma2(xv[k], w[o * 8 + k], acc);
                a[p][o] = relu2(acc);
            }
        }
    }

    // ---- stages 2..4: hidden layers (5 -> relu(5)) ----
    hidden_stage(a, s + OFF_W2, s + OFF_B2);
    hidden_stage(a, s + OFF_W3, s + OFF_B3);
    hidden_stage(a, s + OFF_W4, s + OFF_B4);

    // ---- stage 5: output layer (5 -> relu(4)) + store ----
    {
        u64 w[20], bb[4];
#pragma unroll
        for (int i = 0; i < 20; i++) w[i] = pack1(s[OFF_W5 + i]);
#pragma unroll
        for (int i = 0; i < 4; i++) bb[i] = pack1(s[OFF_B5 + i]);

#pragma unroll
        for (int p = 0; p < PAIRS; p++) {
            float lo[4], hi[4];
#pragma unroll
            for (int o = 0; o < 4; o++) {
                u64 acc = bb[o];
#pragma unroll
                for (int k = 0; k < 5; k++) acc = fma2(a[p][k], w[o * 5 + k], acc);
                acc = relu2(acc);
                unpack2(acc, lo[o], hi[o]);
            }
            const int r0 = idx + (2 * p) * CHUNK;
            const int r1 = idx + (2 * p + 1) * CHUNK;
            out[r0] = make_float4(lo[0], lo[1], lo[2], lo[3]);
            out[r1] = make_float4(hi[0], hi[1], hi[2], hi[3]);
        }
    }
}

extern "C" void kernel_launch(void* const* d_in, const int* in_sizes, int n_in,
                              void* d_out, int out_size) {
    const float* x  = (const float*)d_in[0];
    const float* W0 = (const float*)d_in[1];
    const float* b0 = (const float*)d_in[2];
    const float* W1 = (const float*)d_in[3];
    const float* b1 = (const float*)d_in[4];
    const float* W2 = (const float*)d_in[5];
    const float* b2 = (const float*)d_in[6];
    const float* W3 = (const float*)d_in[7];
    const float* b3 = (const float*)d_in[8];
    const float* W4 = (const float*)d_in[9];
    const float* b4 = (const float*)d_in[10];
    const float* W5 = (const float*)d_in[11];
    const float* b5 = (const float*)d_in[12];

    prep_kernel<<<1, 64>>>(W0, b0, W1, b1);

    const int grid = (BATCH / ROWS_PER_THREAD) / NTHREADS;  // 1024
    mlp_kernel<<<grid, NTHREADS>>>((const float4*)x,
                                   W2, b2, W3, b3, W4, b4, W5, b5,
                                   (float4*)d_out);
}